// round 1
// baseline (speedup 1.0000x reference)
#include <cuda_runtime.h>

#define NN    50000
#define DD    128
#define EE    600000
#define NPRED 200000
#define NSEL  300000
#define UD    256

// ---------------- scratch (device globals: allocation-free) ----------------
__device__ int   g_deg_in[NN];
__device__ int   g_deg_out[NN];
__device__ float g_rin[NN];
__device__ float g_rout[NN];
__device__ int   g_off[NN + 1];
__device__ int   g_cur[NN];
__device__ int   g_srcs[EE];
__device__ float g_bufA[(size_t)NN * DD];
__device__ float g_bufB[(size_t)NN * DD];

// ---------------- degree counting ----------------
__global__ void k_zero() {
    int i = blockIdx.x * blockDim.x + threadIdx.x;
    if (i < NN) { g_deg_in[i] = 0; g_deg_out[i] = 0; }
}

__global__ void k_count(const int* __restrict__ ei) {
    int e = blockIdx.x * blockDim.x + threadIdx.x;
    if (e < EE) {
        atomicAdd(&g_deg_out[ei[e]], 1);        // src row
        atomicAdd(&g_deg_in[ei[EE + e]], 1);    // dst row
    }
}

__global__ void k_rsqrt() {
    int i = blockIdx.x * blockDim.x + threadIdx.x;
    if (i < NN) {
        int dout = g_deg_out[i]; if (dout < 1) dout = 1;
        int din  = g_deg_in[i];  if (din  < 1) din  = 1;
        g_rout[i] = rsqrtf((float)dout);
        g_rin[i]  = rsqrtf((float)din);
    }
}

// ---------------- single-block exclusive scan of deg_in -> off ----------------
__global__ void k_scan() {
    __shared__ int sh[1024];
    __shared__ int s_run;
    int tid = threadIdx.x;
    if (tid == 0) s_run = 0;
    __syncthreads();
    for (int base = 0; base < NN; base += 1024) {
        int i = base + tid;
        int v = (i < NN) ? g_deg_in[i] : 0;
        sh[tid] = v;
        __syncthreads();
        for (int s = 1; s < 1024; s <<= 1) {
            int t = (tid >= s) ? sh[tid - s] : 0;
            __syncthreads();
            sh[tid] += t;
            __syncthreads();
        }
        int incl  = sh[tid];
        int total = sh[1023];
        int run   = s_run;
        if (i < NN) {
            int off = run + incl - v;
            g_off[i] = off;
            g_cur[i] = off;
        }
        __syncthreads();
        if (tid == 0) s_run += total;
        __syncthreads();
    }
    if (tid == 0) g_off[NN] = s_run;
}

// ---------------- CSR fill: slot per incoming edge ----------------
__global__ void k_fill(const int* __restrict__ ei) {
    int e = blockIdx.x * blockDim.x + threadIdx.x;
    if (e < EE) {
        int d = ei[EE + e];
        int slot = atomicAdd(&g_cur[d], 1);
        g_srcs[slot] = ei[e];
    }
}

// ---------------- conv GEMM: g_bufA = (X * rout) @ W  (N x 128 @ 128 x 128) ----
// M-tile 64, 256 threads, 8x4 micro-tile per thread. Dynamic smem 96 KB.
__global__ void k_gemm128(const float* __restrict__ Xext,
                          const float* __restrict__ W, int useB) {
    extern __shared__ float sm[];
    float* Ws = sm;               // 128*128
    float* Xs = sm + DD * DD;     // 64*128
    const float* X = useB ? (const float*)g_bufB : Xext;

    int tid = threadIdx.x;
    int m0  = blockIdx.x * 64;

    // load W (16384 floats)
    {
        const float4* W4 = (const float4*)W;
        float4* Wd = (float4*)Ws;
        #pragma unroll
        for (int i = 0; i < 16; i++) Wd[tid + 256 * i] = W4[tid + 256 * i];
    }
    // load + scale X tile (64 x 128)
    {
        int r  = tid >> 2;
        int c4 = tid & 3;
        int gi = m0 + r;
        float4* Xd = (float4*)(Xs + r * DD);
        if (gi < NN) {
            float sc = g_rout[gi];
            const float4* Xr = (const float4*)(X + (size_t)gi * DD);
            #pragma unroll
            for (int q = 0; q < 8; q++) {
                float4 v = Xr[c4 + 4 * q];
                v.x *= sc; v.y *= sc; v.z *= sc; v.w *= sc;
                Xd[c4 + 4 * q] = v;
            }
        } else {
            #pragma unroll
            for (int q = 0; q < 8; q++) Xd[c4 + 4 * q] = make_float4(0.f, 0.f, 0.f, 0.f);
        }
    }
    __syncthreads();

    int ty = tid >> 5, tx = tid & 31;
    float acc[8][4];
    #pragma unroll
    for (int r = 0; r < 8; r++)
        #pragma unroll
        for (int c = 0; c < 4; c++) acc[r][c] = 0.f;

    #pragma unroll 4
    for (int k = 0; k < DD; k++) {
        float a[8], b[4];
        #pragma unroll
        for (int r = 0; r < 8; r++) a[r] = Xs[(ty * 8 + r) * DD + k];
        #pragma unroll
        for (int c = 0; c < 4; c++) b[c] = Ws[k * DD + tx + 32 * c];
        #pragma unroll
        for (int r = 0; r < 8; r++)
            #pragma unroll
            for (int c = 0; c < 4; c++) acc[r][c] = fmaf(a[r], b[c], acc[r][c]);
    }

    #pragma unroll
    for (int r = 0; r < 8; r++) {
        int gi = m0 + ty * 8 + r;
        if (gi < NN) {
            #pragma unroll
            for (int c = 0; c < 4; c++)
                g_bufA[(size_t)gi * DD + tx + 32 * c] = acc[r][c];
        }
    }
}

// ---------------- aggregation: bufB[i] = rin[i] * sum_{src in in(i)} bufA[src] + b --
// warp per node, float4 lanes (L2-resident gather)
__global__ void k_agg(const float* __restrict__ bias) {
    int t = blockIdx.x * blockDim.x + threadIdx.x;
    int w = t >> 5, lane = t & 31;
    if (w >= NN) return;
    int lo = g_off[w], hi = g_off[w + 1];
    float4 acc = make_float4(0.f, 0.f, 0.f, 0.f);
    for (int j = lo; j < hi; j++) {
        int s = g_srcs[j];
        float4 v = *(const float4*)(g_bufA + (size_t)s * DD + lane * 4);
        acc.x += v.x; acc.y += v.y; acc.z += v.z; acc.w += v.w;
    }
    float r = g_rin[w];
    float4 bb = *(const float4*)(bias + lane * 4);
    float4 o;
    o.x = acc.x * r + bb.x; o.y = acc.y * r + bb.y;
    o.z = acc.z * r + bb.z; o.w = acc.w * r + bb.w;
    *(float4*)(g_bufB + (size_t)w * DD + lane * 4) = o;
}

// ---------------- fused gather + dense(128->256,relu) + out(256->2) + softmax ----
// M-tile 64, 256 threads, 8x8 micro-tile. Dynamic smem ~163 KB.
__global__ void k_final(const int* __restrict__ set_idx,
                        const int* __restrict__ oe,      // flattened [2, NPRED]
                        const float* __restrict__ dW,
                        const float* __restrict__ db,
                        const float* __restrict__ oW,
                        const float* __restrict__ ob,
                        float* __restrict__ out) {
    extern __shared__ float sm[];
    float* Ws   = sm;                  // 128*256
    float* Xs   = Ws + DD * UD;        // 64*128
    float* s_db = Xs + 64 * DD;        // 256
    float* s_oW = s_db + UD;           // 512
    __shared__ float s_ob[2];

    int tid = threadIdx.x;
    int m0  = blockIdx.x * 64;

    // load dense_W (32768 floats = 8192 float4)
    {
        const float4* W4 = (const float4*)dW;
        float4* Wd = (float4*)Ws;
        #pragma unroll
        for (int i = 0; i < 32; i++) Wd[tid + 256 * i] = W4[tid + 256 * i];
    }
    if (tid < UD) {
        s_db[tid]        = db[tid];
        s_oW[tid * 2]    = oW[tid * 2];
        s_oW[tid * 2 + 1] = oW[tid * 2 + 1];
    }
    if (tid < 2) s_ob[tid] = ob[tid];

    // gather 64 rows of h2 via set_idx -> flattened out_edges
    {
        int r  = tid >> 2;
        int c4 = tid & 3;
        int gi = m0 + r;
        float4* Xd = (float4*)(Xs + r * DD);
        if (gi < NSEL) {
            int s    = set_idx[gi];        // in [0, 2*NPRED)
            int node = oe[s];              // concat == flat indexing
            const float4* Hs = (const float4*)(g_bufB + (size_t)node * DD);
            #pragma unroll
            for (int q = 0; q < 8; q++) Xd[c4 + 4 * q] = Hs[c4 + 4 * q];
        } else {
            #pragma unroll
            for (int q = 0; q < 8; q++) Xd[c4 + 4 * q] = make_float4(0.f, 0.f, 0.f, 0.f);
        }
    }
    __syncthreads();

    int ty = tid >> 5, tx = tid & 31;
    float acc[8][8];
    #pragma unroll
    for (int r = 0; r < 8; r++)
        #pragma unroll
        for (int c = 0; c < 8; c++) acc[r][c] = 0.f;

    #pragma unroll 2
    for (int k = 0; k < DD; k++) {
        float a[8], b[8];
        #pragma unroll
        for (int r = 0; r < 8; r++) a[r] = Xs[(ty * 8 + r) * DD + k];
        #pragma unroll
        for (int c = 0; c < 8; c++) b[c] = Ws[k * UD + tx + 32 * c];
        #pragma unroll
        for (int r = 0; r < 8; r++)
            #pragma unroll
            for (int c = 0; c < 8; c++) acc[r][c] = fmaf(a[r], b[c], acc[r][c]);
    }

    // epilogue: relu + 256->2 + softmax
    #pragma unroll
    for (int r = 0; r < 8; r++) {
        float p0 = 0.f, p1 = 0.f;
        #pragma unroll
        for (int c = 0; c < 8; c++) {
            int col = tx + 32 * c;
            float h = acc[r][c] + s_db[col];
            h = fmaxf(h, 0.f);
            p0 = fmaf(h, s_oW[col * 2],     p0);
            p1 = fmaf(h, s_oW[col * 2 + 1], p1);
        }
        #pragma unroll
        for (int o = 16; o; o >>= 1) {
            p0 += __shfl_down_sync(0xffffffffu, p0, o);
            p1 += __shfl_down_sync(0xffffffffu, p1, o);
        }
        if (tx == 0) {
            int gi = m0 + ty * 8 + r;
            if (gi < NSEL) {
                float z0 = p0 + s_ob[0], z1 = p1 + s_ob[1];
                float m  = fmaxf(z0, z1);
                float e0 = __expf(z0 - m), e1 = __expf(z1 - m);
                float inv = 1.f / (e0 + e1);
                out[(size_t)gi * 2]     = e0 * inv;
                out[(size_t)gi * 2 + 1] = e1 * inv;
            }
        }
    }
}

// ---------------- host launch ----------------
extern "C" void kernel_launch(void* const* d_in, const int* in_sizes, int n_in,
                              void* d_out, int out_size) {
    const float* node_state = (const float*)d_in[0];
    const int*   edge_index = (const int*)d_in[1];
    const int*   out_edges  = (const int*)d_in[2];
    const int*   set_idx    = (const int*)d_in[3];
    const float* W1         = (const float*)d_in[4];
    const float* b1         = (const float*)d_in[5];
    const float* W2         = (const float*)d_in[6];
    const float* b2         = (const float*)d_in[7];
    const float* dW         = (const float*)d_in[8];
    const float* db         = (const float*)d_in[9];
    const float* oW         = (const float*)d_in[10];
    const float* ob         = (const float*)d_in[11];
    float* out = (float*)d_out;

    const int GEMM_SMEM  = (DD * DD + 64 * DD) * 4;                 // 96 KB
    const int FINAL_SMEM = (DD * UD + 64 * DD + UD + 2 * UD) * 4;   // ~163 KB

    cudaFuncSetAttribute(k_gemm128, cudaFuncAttributeMaxDynamicSharedMemorySize, GEMM_SMEM);
    cudaFuncSetAttribute(k_final,   cudaFuncAttributeMaxDynamicSharedMemorySize, FINAL_SMEM);

    k_zero <<<(NN + 255) / 256, 256>>>();
    k_count<<<(EE + 255) / 256, 256>>>(edge_index);
    k_rsqrt<<<(NN + 255) / 256, 256>>>();
    k_scan <<<1, 1024>>>();
    k_fill <<<(EE + 255) / 256, 256>>>(edge_index);

    // layer 1: bufA = (node_state * rout) @ W1 ; bufB = agg * rin + b1
    k_gemm128<<<(NN + 63) / 64, 256, GEMM_SMEM>>>(node_state, W1, 0);
    k_agg    <<<(NN * 32 + 255) / 256, 256>>>(b1);
    // layer 2
    k_gemm128<<<(NN + 63) / 64, 256, GEMM_SMEM>>>(nullptr, W2, 1);
    k_agg    <<<(NN * 32 + 255) / 256, 256>>>(b2);

    // fused head
    k_final<<<(NSEL + 63) / 64, 256, FINAL_SMEM>>>(set_idx, out_edges, dW, db, oW, ob, out);
}

// round 3
// speedup vs baseline: 1.1550x; 1.1550x over previous
#include <cuda_runtime.h>

#define NN    50000
#define DD    128
#define EE    600000
#define NPRED 200000
#define NSEL  300000
#define UD    256

typedef unsigned long long ull;

// packed f32x2 helpers (sm_103a FFMA2 — only reachable via PTX)
#define FMA2(d, a, b) asm("fma.rn.f32x2 %0, %1, %2, %0;" : "+l"(d) : "l"(a), "l"(b))
#define PACK2(d, lo, hi) asm("mov.b64 %0, {%1, %2};" : "=l"(d) : "f"(lo), "f"(hi))
#define UNPACK2(lo, hi, s) asm("mov.b64 {%0, %1}, %2;" : "=f"(lo), "=f"(hi) : "l"(s))

// ---------------- scratch (device globals: allocation-free) ----------------
__device__ int   g_deg_in[NN];
__device__ int   g_deg_out[NN];
__device__ float g_rin[NN];
__device__ float g_rout[NN];
__device__ int   g_off[NN + 1];
__device__ int   g_cur[NN];
__device__ int   g_srcs[EE];
__device__ float g_bufA[(size_t)NN * DD];
__device__ float g_bufB[(size_t)NN * DD];

// ---------------- degree counting ----------------
__global__ void k_zero() {
    int i = blockIdx.x * blockDim.x + threadIdx.x;
    if (i < NN) { g_deg_in[i] = 0; g_deg_out[i] = 0; }
}

__global__ void k_count(const int* __restrict__ ei) {
    int e = blockIdx.x * blockDim.x + threadIdx.x;
    if (e < EE) {
        atomicAdd(&g_deg_out[ei[e]], 1);
        atomicAdd(&g_deg_in[ei[EE + e]], 1);
    }
}

__global__ void k_rsqrt() {
    int i = blockIdx.x * blockDim.x + threadIdx.x;
    if (i < NN) {
        int dout = g_deg_out[i]; if (dout < 1) dout = 1;
        int din  = g_deg_in[i];  if (din  < 1) din  = 1;
        g_rout[i] = rsqrtf((float)dout);
        g_rin[i]  = rsqrtf((float)din);
    }
}

// ---------------- fast single-block scan: chunk-per-thread + shfl scans ------
__global__ void k_scan() {
    __shared__ int warp_tot[32];
    int tid  = threadIdx.x;
    int lane = tid & 31, wid = tid >> 5;
    const int C = (NN + 1023) / 1024;       // 49
    int lo = tid * C;
    int hi = lo + C; if (hi > NN) hi = NN;
    if (lo > NN) lo = NN;

    int sum = 0;
    for (int i = lo; i < hi; i++) sum += g_deg_in[i];

    // warp inclusive scan of chunk sums
    int x = sum;
    #pragma unroll
    for (int s = 1; s < 32; s <<= 1) {
        int v = __shfl_up_sync(0xffffffffu, x, s);
        if (lane >= s) x += v;
    }
    if (lane == 31) warp_tot[wid] = x;
    __syncthreads();
    if (wid == 0) {
        int y = warp_tot[lane];
        #pragma unroll
        for (int s = 1; s < 32; s <<= 1) {
            int v = __shfl_up_sync(0xffffffffu, y, s);
            if (lane >= s) y += v;
        }
        warp_tot[lane] = y;
    }
    __syncthreads();

    int run = x - sum + (wid ? warp_tot[wid - 1] : 0);  // exclusive prefix
    for (int i = lo; i < hi; i++) {
        g_off[i] = run; g_cur[i] = run;
        run += g_deg_in[i];
    }
    if (tid == 1023) g_off[NN] = run;   // last chunk empty -> run == grand total
}

// ---------------- CSR fill ----------------
__global__ void k_fill(const int* __restrict__ ei) {
    int e = blockIdx.x * blockDim.x + threadIdx.x;
    if (e < EE) {
        int d = ei[EE + e];
        int slot = atomicAdd(&g_cur[d], 1);
        g_srcs[slot] = ei[e];
    }
}

// ---------------- conv GEMM (f32x2): bufA = (X * rout) @ W  (N x 128 @ 128 x 128)
// M-tile 64, 256 threads. Thread tx -> cols [4tx, 4tx+4). Dynamic smem 96 KB.
__global__ void __launch_bounds__(256, 2)
k_gemm128(const float* __restrict__ Xext, const float* __restrict__ W, int useB) {
    extern __shared__ float sm[];
    float* Ws = sm;               // 128*128
    float* Xs = sm + DD * DD;     // 64*128
    const float* X = useB ? (const float*)g_bufB : Xext;

    int tid = threadIdx.x;
    int m0  = blockIdx.x * 64;

    {
        const float4* W4 = (const float4*)W;
        float4* Wd = (float4*)Ws;
        #pragma unroll
        for (int i = 0; i < 16; i++) Wd[tid + 256 * i] = W4[tid + 256 * i];
    }
    {
        int r  = tid >> 2;
        int c4 = tid & 3;
        int gi = m0 + r;
        float4* Xd = (float4*)(Xs + r * DD);
        if (gi < NN) {
            float sc = g_rout[gi];
            const float4* Xr = (const float4*)(X + (size_t)gi * DD);
            #pragma unroll
            for (int q = 0; q < 8; q++) {
                float4 v = Xr[c4 + 4 * q];
                v.x *= sc; v.y *= sc; v.z *= sc; v.w *= sc;
                Xd[c4 + 4 * q] = v;
            }
        } else {
            #pragma unroll
            for (int q = 0; q < 8; q++) Xd[c4 + 4 * q] = make_float4(0.f, 0.f, 0.f, 0.f);
        }
    }
    __syncthreads();

    int ty = tid >> 5, tx = tid & 31;
    ull acc[8][2];
    #pragma unroll
    for (int r = 0; r < 8; r++) { acc[r][0] = 0ull; acc[r][1] = 0ull; }

    #pragma unroll 4
    for (int k = 0; k < DD; k++) {
        float4 bv = *(const float4*)(Ws + k * DD + 4 * tx);
        ull b0, b1;
        PACK2(b0, bv.x, bv.y);
        PACK2(b1, bv.z, bv.w);
        #pragma unroll
        for (int r = 0; r < 8; r++) {
            float a = Xs[(ty * 8 + r) * DD + k];     // warp broadcast
            ull a2; PACK2(a2, a, a);
            FMA2(acc[r][0], a2, b0);
            FMA2(acc[r][1], a2, b1);
        }
    }

    #pragma unroll
    for (int r = 0; r < 8; r++) {
        int gi = m0 + ty * 8 + r;
        if (gi < NN) {
            float4 o;
            UNPACK2(o.x, o.y, acc[r][0]);
            UNPACK2(o.z, o.w, acc[r][1]);
            *(float4*)(g_bufA + (size_t)gi * DD + 4 * tx) = o;
        }
    }
}

// ---------------- aggregation: bufB[i] = rin[i]*sum_{in(i)} bufA[src] + b ----
__global__ void k_agg(const float* __restrict__ bias) {
    int t = blockIdx.x * blockDim.x + threadIdx.x;
    int w = t >> 5, lane = t & 31;
    if (w >= NN) return;
    int lo = g_off[w], hi = g_off[w + 1];
    float4 acc = make_float4(0.f, 0.f, 0.f, 0.f);
    for (int j = lo; j < hi; j++) {
        int s = g_srcs[j];
        float4 v = *(const float4*)(g_bufA + (size_t)s * DD + lane * 4);
        acc.x += v.x; acc.y += v.y; acc.z += v.z; acc.w += v.w;
    }
    float r = g_rin[w];
    float4 bb = *(const float4*)(bias + lane * 4);
    float4 o;
    o.x = acc.x * r + bb.x; o.y = acc.y * r + bb.y;
    o.z = acc.z * r + bb.z; o.w = acc.w * r + bb.w;
    *(float4*)(g_bufB + (size_t)w * DD + lane * 4) = o;
}

// ---------------- fused gather + dense(128->256,relu) + out(256->2) + softmax
// M-tile 64, 256 threads, f32x2 mainloop. Thread tx -> cols [8tx, 8tx+8).
__global__ void __launch_bounds__(256, 1)
k_final(const int* __restrict__ set_idx,
        const int* __restrict__ oe,
        const float* __restrict__ dW,
        const float* __restrict__ db,
        const float* __restrict__ oW,
        const float* __restrict__ ob,
        float* __restrict__ out) {
    extern __shared__ float sm[];
    float* Ws   = sm;                  // 128*256
    float* Xs   = Ws + DD * UD;        // 64*128
    float* s_db = Xs + 64 * DD;        // 256
    float* s_oW = s_db + UD;           // 512
    __shared__ float s_ob[2];

    int tid = threadIdx.x;
    int m0  = blockIdx.x * 64;

    {
        const float4* W4 = (const float4*)dW;
        float4* Wd = (float4*)Ws;
        #pragma unroll
        for (int i = 0; i < 32; i++) Wd[tid + 256 * i] = W4[tid + 256 * i];
    }
    if (tid < UD) {
        s_db[tid]         = db[tid];
        s_oW[tid * 2]     = oW[tid * 2];
        s_oW[tid * 2 + 1] = oW[tid * 2 + 1];
    }
    if (tid < 2) s_ob[tid] = ob[tid];

    {
        int r  = tid >> 2;
        int c4 = tid & 3;
        int gi = m0 + r;
        float4* Xd = (float4*)(Xs + r * DD);
        if (gi < NSEL) {
            int s    = set_idx[gi];
            int node = oe[s];
            const float4* Hs = (const float4*)(g_bufB + (size_t)node * DD);
            #pragma unroll
            for (int q = 0; q < 8; q++) Xd[c4 + 4 * q] = Hs[c4 + 4 * q];
        } else {
            #pragma unroll
            for (int q = 0; q < 8; q++) Xd[c4 + 4 * q] = make_float4(0.f, 0.f, 0.f, 0.f);
        }
    }
    __syncthreads();

    int ty = tid >> 5, tx = tid & 31;
    ull acc[8][4];
    #pragma unroll
    for (int r = 0; r < 8; r++)
        #pragma unroll
        for (int c = 0; c < 4; c++) acc[r][c] = 0ull;

    #pragma unroll 2
    for (int k = 0; k < DD; k++) {
        float4 bv0 = *(const float4*)(Ws + k * UD + 8 * tx);
        float4 bv1 = *(const float4*)(Ws + k * UD + 8 * tx + 4);
        ull b[4];
        PACK2(b[0], bv0.x, bv0.y);
        PACK2(b[1], bv0.z, bv0.w);
        PACK2(b[2], bv1.x, bv1.y);
        PACK2(b[3], bv1.z, bv1.w);
        #pragma unroll
        for (int r = 0; r < 8; r++) {
            float a = Xs[(ty * 8 + r) * DD + k];     // warp broadcast
            ull a2; PACK2(a2, a, a);
            #pragma unroll
            for (int c = 0; c < 4; c++) FMA2(acc[r][c], a2, b[c]);
        }
    }

    // epilogue: relu + 256->2 + softmax
    #pragma unroll
    for (int r = 0; r < 8; r++) {
        float p0 = 0.f, p1 = 0.f;
        #pragma unroll
        for (int c = 0; c < 4; c++) {
            float h0, h1;
            UNPACK2(h0, h1, acc[r][c]);
            int col0 = 8 * tx + 2 * c;
            float v0 = fmaxf(h0 + s_db[col0],     0.f);
            float v1 = fmaxf(h1 + s_db[col0 + 1], 0.f);
            p0 = fmaf(v0, s_oW[col0 * 2],       p0);
            p1 = fmaf(v0, s_oW[col0 * 2 + 1],   p1);
            p0 = fmaf(v1, s_oW[col0 * 2 + 2],   p0);
            p1 = fmaf(v1, s_oW[col0 * 2 + 3],   p1);
        }
        #pragma unroll
        for (int o = 16; o; o >>= 1) {
            p0 += __shfl_down_sync(0xffffffffu, p0, o);
            p1 += __shfl_down_sync(0xffffffffu, p1, o);
        }
        if (tx == 0) {
            int gi = m0 + ty * 8 + r;
            if (gi < NSEL) {
                float z0 = p0 + s_ob[0], z1 = p1 + s_ob[1];
                float m  = fmaxf(z0, z1);
                float e0 = __expf(z0 - m), e1 = __expf(z1 - m);
                float inv = 1.f / (e0 + e1);
                out[(size_t)gi * 2]     = e0 * inv;
                out[(size_t)gi * 2 + 1] = e1 * inv;
            }
        }
    }
}

// ---------------- host launch ----------------
extern "C" void kernel_launch(void* const* d_in, const int* in_sizes, int n_in,
                              void* d_out, int out_size) {
    const float* node_state = (const float*)d_in[0];
    const int*   edge_index = (const int*)d_in[1];
    const int*   out_edges  = (const int*)d_in[2];
    const int*   set_idx    = (const int*)d_in[3];
    const float* W1         = (const float*)d_in[4];
    const float* b1         = (const float*)d_in[5];
    const float* W2         = (const float*)d_in[6];
    const float* b2         = (const float*)d_in[7];
    const float* dW         = (const float*)d_in[8];
    const float* db         = (const float*)d_in[9];
    const float* oW         = (const float*)d_in[10];
    const float* ob         = (const float*)d_in[11];
    float* out = (float*)d_out;

    const int GEMM_SMEM  = (DD * DD + 64 * DD) * 4;                 // 96 KB
    const int FINAL_SMEM = (DD * UD + 64 * DD + UD + 2 * UD) * 4;   // ~163 KB

    cudaFuncSetAttribute(k_gemm128, cudaFuncAttributeMaxDynamicSharedMemorySize, GEMM_SMEM);
    cudaFuncSetAttribute(k_final,   cudaFuncAttributeMaxDynamicSharedMemorySize, FINAL_SMEM);

    k_zero <<<(NN + 255) / 256, 256>>>();
    k_count<<<(EE + 255) / 256, 256>>>(edge_index);
    k_rsqrt<<<(NN + 255) / 256, 256>>>();
    k_scan <<<1, 1024>>>();
    k_fill <<<(EE + 255) / 256, 256>>>(edge_index);

    k_gemm128<<<(NN + 63) / 64, 256, GEMM_SMEM>>>(node_state, W1, 0);
    k_agg    <<<(NN * 32 + 255) / 256, 256>>>(b1);
    k_gemm128<<<(NN + 63) / 64, 256, GEMM_SMEM>>>(nullptr, W2, 1);
    k_agg    <<<(NN * 32 + 255) / 256, 256>>>(b2);

    k_final<<<(NSEL + 63) / 64, 256, FINAL_SMEM>>>(set_idx, out_edges, dW, db, oW, ob, out);
}

// round 5
// speedup vs baseline: 1.2607x; 1.0915x over previous
#include <cuda_runtime.h>

#define NN    50000
#define DD    128
#define EE    600000
#define NPRED 200000
#define NSEL  300000
#define UD    256
#define NB    49          // scan blocks: 49*1024 >= NN

typedef unsigned long long ull;

// packed f32x2 helpers (sm_103a FFMA2 — only reachable via PTX)
#define FMA2(d, a, b) asm("fma.rn.f32x2 %0, %1, %2, %0;" : "+l"(d) : "l"(a), "l"(b))
#define UNPACK2(lo, hi, s) asm("mov.b64 {%0, %1}, %2;" : "=f"(lo), "=f"(hi) : "l"(s))

// ---------------- scratch (device globals: allocation-free) ----------------
__device__ int   g_deg_in[NN];
__device__ int   g_deg_out[NN];
__device__ float g_rin[NN];
__device__ float g_rout[NN];
__device__ int   g_off[NN + 1];
__device__ int   g_cur[NN];
__device__ int   g_srcs[EE];
__device__ int   g_bsum[NB];
__device__ int   g_bpre[NB];
__device__ float g_bufA[(size_t)NN * DD];
__device__ float g_bufB[(size_t)NN * DD];

// ---------------- degree counting ----------------
__global__ void k_zero() {
    int i = blockIdx.x * blockDim.x + threadIdx.x;
    if (i < NN) { g_deg_in[i] = 0; g_deg_out[i] = 0; }
}

__global__ void k_count(const int* __restrict__ ei) {
    int e = blockIdx.x * blockDim.x + threadIdx.x;
    if (e < EE) {
        atomicAdd(&g_deg_out[ei[e]], 1);
        atomicAdd(&g_deg_in[ei[EE + e]], 1);
    }
}

__global__ void k_rsqrt() {
    int i = blockIdx.x * blockDim.x + threadIdx.x;
    if (i < NN) {
        int dout = g_deg_out[i]; if (dout < 1) dout = 1;
        int din  = g_deg_in[i];  if (din  < 1) din  = 1;
        g_rout[i] = rsqrtf((float)dout);
        g_rin[i]  = rsqrtf((float)din);
    }
}

// ---------------- hierarchical scan (coalesced, multi-SM) ----------------
__global__ void k_scan_a() {
    __shared__ int wsum[32];
    int tid  = threadIdx.x;
    int i    = blockIdx.x * 1024 + tid;
    int lane = tid & 31, wid = tid >> 5;
    int v = (i < NN) ? g_deg_in[i] : 0;

    int x = v;
    #pragma unroll
    for (int s = 1; s < 32; s <<= 1) {
        int t = __shfl_up_sync(0xffffffffu, x, s);
        if (lane >= s) x += t;
    }
    if (lane == 31) wsum[wid] = x;
    __syncthreads();
    if (wid == 0) {
        int y = wsum[lane];
        #pragma unroll
        for (int s = 1; s < 32; s <<= 1) {
            int t = __shfl_up_sync(0xffffffffu, y, s);
            if (lane >= s) y += t;
        }
        wsum[lane] = y;
    }
    __syncthreads();

    int excl = x - v + (wid ? wsum[wid - 1] : 0);
    if (i < NN) g_off[i] = excl;
    if (tid == 1023) g_bsum[blockIdx.x] = excl + v;
}

__global__ void k_scan_b() {
    int run = 0;
    #pragma unroll
    for (int b = 0; b < NB; b++) { int t = g_bsum[b]; g_bpre[b] = run; run += t; }
    g_off[NN] = run;
}

__global__ void k_scan_c() {
    int i = blockIdx.x * 1024 + threadIdx.x;
    if (i < NN) {
        int o = g_off[i] + g_bpre[blockIdx.x];
        g_off[i] = o;
        g_cur[i] = o;
    }
}

// ---------------- CSR fill ----------------
__global__ void k_fill(const int* __restrict__ ei) {
    int e = blockIdx.x * blockDim.x + threadIdx.x;
    if (e < EE) {
        int d = ei[EE + e];
        int slot = atomicAdd(&g_cur[d], 1);
        g_srcs[slot] = ei[e];
    }
}

// ---------------- conv GEMM (k-pair f32x2): bufA = (X*rout) @ W  (Nx128 @ 128x128)
__global__ void __launch_bounds__(256, 2)
k_gemm128(const float* __restrict__ Xext, const float* __restrict__ W, int useB) {
    extern __shared__ float sm[];
    float* Ws2 = sm;              // 128*128 floats (64 kp x 128 cols x float2)
    float* Xs  = sm + DD * DD;    // 64*128
    const float* X = useB ? (const float*)g_bufB : Xext;

    int tid = threadIdx.x;
    int m0  = blockIdx.x * 64;

    {
        float2* Wd = (float2*)Ws2;
        #pragma unroll
        for (int q = 0; q < 32; q++) {
            int idx = tid + 256 * q;          // 0..8191
            int kp = idx >> 7, c = idx & 127;
            Wd[idx] = make_float2(W[(2 * kp) * DD + c], W[(2 * kp + 1) * DD + c]);
        }
    }
    {
        int r  = tid >> 2;
        int c4 = tid & 3;
        int gi = m0 + r;
        float4* Xd = (float4*)(Xs + r * DD);
        if (gi < NN) {
            float sc = g_rout[gi];
            const float4* Xr = (const float4*)(X + (size_t)gi * DD);
            #pragma unroll
            for (int q = 0; q < 8; q++) {
                float4 v = Xr[c4 + 4 * q];
                v.x *= sc; v.y *= sc; v.z *= sc; v.w *= sc;
                Xd[c4 + 4 * q] = v;
            }
        } else {
            #pragma unroll
            for (int q = 0; q < 8; q++) Xd[c4 + 4 * q] = make_float4(0.f, 0.f, 0.f, 0.f);
        }
    }
    __syncthreads();

    int ty = tid >> 5, tx = tid & 31;
    const ull* Wp = (const ull*)Ws2;            // [kp*128 + col]
    ull acc[8][4];
    #pragma unroll
    for (int r = 0; r < 8; r++)
        #pragma unroll
        for (int c = 0; c < 4; c++) acc[r][c] = 0ull;

    #pragma unroll 8
    for (int kp = 0; kp < DD / 2; kp++) {
        ulonglong2 bb0 = *(const ulonglong2*)(Wp + kp * DD + 4 * tx);
        ulonglong2 bb1 = *(const ulonglong2*)(Wp + kp * DD + 4 * tx + 2);
        ull a2[8];
        #pragma unroll
        for (int r = 0; r < 8; r++)
            a2[r] = *(const ull*)(Xs + (ty * 8 + r) * DD + 2 * kp);   // broadcast
        #pragma unroll
        for (int r = 0; r < 8; r++) {
            FMA2(acc[r][0], a2[r], bb0.x);
            FMA2(acc[r][1], a2[r], bb0.y);
            FMA2(acc[r][2], a2[r], bb1.x);
            FMA2(acc[r][3], a2[r], bb1.y);
        }
    }

    #pragma unroll
    for (int r = 0; r < 8; r++) {
        int gi = m0 + ty * 8 + r;
        if (gi < NN) {
            float4 o;
            float lo, hi;
            UNPACK2(lo, hi, acc[r][0]); o.x = lo + hi;
            UNPACK2(lo, hi, acc[r][1]); o.y = lo + hi;
            UNPACK2(lo, hi, acc[r][2]); o.z = lo + hi;
            UNPACK2(lo, hi, acc[r][3]); o.w = lo + hi;
            *(float4*)(g_bufA + (size_t)gi * DD + 4 * tx) = o;
        }
    }
}

// ---------------- aggregation: bufB[i] = rin[i]*sum_{in(i)} bufA[src] + b ----
__global__ void k_agg(const float* __restrict__ bias) {
    int t = blockIdx.x * blockDim.x + threadIdx.x;
    int w = t >> 5, lane = t & 31;
    if (w >= NN) return;
    int lo = g_off[w], hi = g_off[w + 1];
    float4 acc = make_float4(0.f, 0.f, 0.f, 0.f);
    for (int j = lo; j < hi; j++) {
        int s = g_srcs[j];
        float4 v = *(const float4*)(g_bufA + (size_t)s * DD + lane * 4);
        acc.x += v.x; acc.y += v.y; acc.z += v.z; acc.w += v.w;
    }
    float r = g_rin[w];
    float4 bb = *(const float4*)(bias + lane * 4);
    float4 o;
    o.x = acc.x * r + bb.x; o.y = acc.y * r + bb.y;
    o.z = acc.z * r + bb.z; o.w = acc.w * r + bb.w;
    *(float4*)(g_bufB + (size_t)w * DD + lane * 4) = o;
}

// ---------------- fused gather + dense(128->256,relu) + out(256->2) + softmax
// 512 THREADS. ty=tid>>6 (8 row-groups x 8 rows), tx=tid&63 -> cols [4tx,4tx+4).
__global__ void __launch_bounds__(512, 1)
k_final(const int* __restrict__ set_idx,
        const int* __restrict__ oe,
        const float* __restrict__ dW,
        const float* __restrict__ db,
        const float* __restrict__ oW,
        const float* __restrict__ ob,
        float* __restrict__ out) {
    extern __shared__ float sm[];
    float* Ws2   = sm;                  // 128*256 floats (64 kp x 256 cols x float2)
    float* Xs    = Ws2 + DD * UD;       // 64*128
    float* s_db  = Xs + 64 * DD;        // 256
    float* s_oW  = s_db + UD;           // 512
    float* s_red = s_oW + 2 * UD;       // 16 warps * 8 rows * 2 = 256
    __shared__ float s_ob[2];

    int tid = threadIdx.x;
    int m0  = blockIdx.x * 64;

    {
        float2* Wd = (float2*)Ws2;
        #pragma unroll
        for (int q = 0; q < 32; q++) {
            int idx = tid + 512 * q;          // 0..16383
            int kp = idx >> 8, c = idx & 255;
            Wd[idx] = make_float2(dW[(2 * kp) * UD + c], dW[(2 * kp + 1) * UD + c]);
        }
    }
    if (tid < UD) {
        s_db[tid]         = db[tid];
        s_oW[tid * 2]     = oW[tid * 2];
        s_oW[tid * 2 + 1] = oW[tid * 2 + 1];
    }
    if (tid < 2) s_ob[tid] = ob[tid];

    {
        int r  = tid >> 3;         // 0..63
        int c4 = tid & 7;          // 0..7
        int gi = m0 + r;
        float4* Xd = (float4*)(Xs + r * DD);
        if (gi < NSEL) {
            int s    = set_idx[gi];
            int node = oe[s];
            const float4* Hs = (const float4*)(g_bufB + (size_t)node * DD);
            #pragma unroll
            for (int q = 0; q < 4; q++) Xd[c4 + 8 * q] = Hs[c4 + 8 * q];
        } else {
            #pragma unroll
            for (int q = 0; q < 4; q++) Xd[c4 + 8 * q] = make_float4(0.f, 0.f, 0.f, 0.f);
        }
    }
    __syncthreads();

    int ty = tid >> 6, tx = tid & 63;
    const ull* Wp = (const ull*)Ws2;            // [kp*256 + col]
    ull acc[8][4];
    #pragma unroll
    for (int r = 0; r < 8; r++)
        #pragma unroll
        for (int c = 0; c < 4; c++) acc[r][c] = 0ull;

    #pragma unroll 8
    for (int kp = 0; kp < DD / 2; kp++) {
        ulonglong2 bb0 = *(const ulonglong2*)(Wp + kp * UD + 4 * tx);
        ulonglong2 bb1 = *(const ulonglong2*)(Wp + kp * UD + 4 * tx + 2);
        ull a2[8];
        #pragma unroll
        for (int r = 0; r < 8; r++)
            a2[r] = *(const ull*)(Xs + (ty * 8 + r) * DD + 2 * kp);   // broadcast
        #pragma unroll
        for (int r = 0; r < 8; r++) {
            FMA2(acc[r][0], a2[r], bb0.x);
            FMA2(acc[r][1], a2[r], bb0.y);
            FMA2(acc[r][2], a2[r], bb1.x);
            FMA2(acc[r][3], a2[r], bb1.y);
        }
    }

    int wid  = tid >> 5;           // 0..15
    int lane = tid & 31;
    #pragma unroll
    for (int r = 0; r < 8; r++) {
        float p0 = 0.f, p1 = 0.f;
        #pragma unroll
        for (int c = 0; c < 4; c++) {
            float lo, hi;
            UNPACK2(lo, hi, acc[r][c]);
            int col = 4 * tx + c;
            float v = fmaxf(lo + hi + s_db[col], 0.f);
            p0 = fmaf(v, s_oW[col * 2],     p0);
            p1 = fmaf(v, s_oW[col * 2 + 1], p1);
        }
        #pragma unroll
        for (int o = 16; o; o >>= 1) {
            p0 += __shfl_down_sync(0xffffffffu, p0, o);
            p1 += __shfl_down_sync(0xffffffffu, p1, o);
        }
        if (lane == 0) {
            s_red[(wid * 8 + r) * 2]     = p0;
            s_red[(wid * 8 + r) * 2 + 1] = p1;
        }
    }
    __syncthreads();

    if (tid < 64) {
        int tg = tid >> 3, r = tid & 7;          // row = tg*8 + r = tid
        float p0 = s_red[((2 * tg) * 8 + r) * 2]     + s_red[((2 * tg + 1) * 8 + r) * 2];
        float p1 = s_red[((2 * tg) * 8 + r) * 2 + 1] + s_red[((2 * tg + 1) * 8 + r) * 2 + 1];
        int gi = m0 + tid;
        if (gi < NSEL) {
            float z0 = p0 + s_ob[0], z1 = p1 + s_ob[1];
            float m  = fmaxf(z0, z1);
            float e0 = __expf(z0 - m), e1 = __expf(z1 - m);
            float inv = 1.f / (e0 + e1);
            out[(size_t)gi * 2]     = e0 * inv;
            out[(size_t)gi * 2 + 1] = e1 * inv;
        }
    }
}

// ---------------- host launch ----------------
extern "C" void kernel_launch(void* const* d_in, const int* in_sizes, int n_in,
                              void* d_out, int out_size) {
    const float* node_state = (const float*)d_in[0];
    const int*   edge_index = (const int*)d_in[1];
    const int*   out_edges  = (const int*)d_in[2];
    const int*   set_idx    = (const int*)d_in[3];
    const float* W1         = (const float*)d_in[4];
    const float* b1         = (const float*)d_in[5];
    const float* W2         = (const float*)d_in[6];
    const float* b2         = (const float*)d_in[7];
    const float* dW         = (const float*)d_in[8];
    const float* db         = (const float*)d_in[9];
    const float* oW         = (const float*)d_in[10];
    const float* ob         = (const float*)d_in[11];
    float* out = (float*)d_out;

    const int GEMM_SMEM  = (DD * DD + 64 * DD) * 4;                           // 96 KB
    const int FINAL_SMEM = (DD * UD + 64 * DD + UD + 2 * UD + 256) * 4 + 16;  // ~164 KB

    cudaFuncSetAttribute(k_gemm128, cudaFuncAttributeMaxDynamicSharedMemorySize, GEMM_SMEM);
    cudaFuncSetAttribute(k_final,   cudaFuncAttributeMaxDynamicSharedMemorySize, FINAL_SMEM);

    k_zero   <<<(NN + 255) / 256, 256>>>();
    k_count  <<<(EE + 255) / 256, 256>>>(edge_index);
    k_rsqrt  <<<(NN + 255) / 256, 256>>>();
    k_scan_a <<<NB, 1024>>>();
    k_scan_b <<<1, 1>>>();
    k_scan_c <<<NB, 1024>>>();
    k_fill   <<<(EE + 255) / 256, 256>>>(edge_index);

    k_gemm128<<<(NN + 63) / 64, 256, GEMM_SMEM>>>(node_state, W1, 0);
    k_agg    <<<(NN * 32 + 255) / 256, 256>>>(b1);
    k_gemm128<<<(NN + 63) / 64, 256, GEMM_SMEM>>>(nullptr, W2, 1);
    k_agg    <<<(NN * 32 + 255) / 256, 256>>>(b2);

    // FIX: k_final is a 512-thread kernel (round-4 regression launched it with 256)
    k_final<<<(NSEL + 63) / 64, 512, FINAL_SMEM>>>(set_idx, out_edges, dW, db, oW, ob, out);
}

// round 6
// speedup vs baseline: 1.3307x; 1.0556x over previous
#include <cuda_runtime.h>

#define NN    50000
#define DD    128
#define EE    600000
#define NPRED 200000
#define NSEL  300000
#define UD    256
#define NB    49          // scan blocks: 49*1024 >= NN
#define NSM   148

typedef unsigned long long ull;

// packed f32x2 helpers (sm_103a FFMA2 — only reachable via PTX)
#define FMA2(d, a, b) asm("fma.rn.f32x2 %0, %1, %2, %0;" : "+l"(d) : "l"(a), "l"(b))
#define UNPACK2(lo, hi, s) asm("mov.b64 {%0, %1}, %2;" : "=f"(lo), "=f"(hi) : "l"(s))

// ---------------- scratch (device globals: allocation-free) ----------------
__device__ int   g_deg_in[NN];
__device__ int   g_deg_out[NN];
__device__ float g_rin[NN];
__device__ float g_rout[NN];
__device__ int   g_off[NN + 1];
__device__ int   g_cur[NN];
__device__ int   g_srcs[EE];
__device__ int   g_bsum[NB];
__device__ float g_bufA[(size_t)NN * DD];
__device__ float g_bufB[(size_t)NN * DD];

// ---------------- degree counting ----------------
__global__ void k_zero() {
    int i = blockIdx.x * blockDim.x + threadIdx.x;
    if (i < NN) { g_deg_in[i] = 0; g_deg_out[i] = 0; }
}

__global__ void k_count(const int* __restrict__ ei) {
    int e = blockIdx.x * blockDim.x + threadIdx.x;
    if (e < EE) {
        atomicAdd(&g_deg_out[ei[e]], 1);
        atomicAdd(&g_deg_in[ei[EE + e]], 1);
    }
}

// ---------------- scan pass A (+ fused rsqrt of both degree arrays) ----------
__global__ void k_scan_a() {
    __shared__ int wsum[32];
    int tid  = threadIdx.x;
    int i    = blockIdx.x * 1024 + tid;
    int lane = tid & 31, wid = tid >> 5;
    int v = (i < NN) ? g_deg_in[i] : 0;

    if (i < NN) {
        int dout = g_deg_out[i]; if (dout < 1) dout = 1;
        int din  = v;            if (din  < 1) din  = 1;
        g_rout[i] = rsqrtf((float)dout);
        g_rin[i]  = rsqrtf((float)din);
    }

    int x = v;
    #pragma unroll
    for (int s = 1; s < 32; s <<= 1) {
        int t = __shfl_up_sync(0xffffffffu, x, s);
        if (lane >= s) x += t;
    }
    if (lane == 31) wsum[wid] = x;
    __syncthreads();
    if (wid == 0) {
        int y = wsum[lane];
        #pragma unroll
        for (int s = 1; s < 32; s <<= 1) {
            int t = __shfl_up_sync(0xffffffffu, y, s);
            if (lane >= s) y += t;
        }
        wsum[lane] = y;
    }
    __syncthreads();

    int excl = x - v + (wid ? wsum[wid - 1] : 0);
    if (i < NN) g_off[i] = excl;
    if (tid == 1023) g_bsum[blockIdx.x] = excl + v;
}

// ---------------- scan pass C (fused block-sum scan, redundant per block) ----
__global__ void k_scan_c() {
    __shared__ int s_pre;
    int tid = threadIdx.x;
    if (tid == 0) {
        int run = 0;
        #pragma unroll
        for (int b = 0; b < NB; b++) {
            if (b == blockIdx.x) s_pre = run;
            run += g_bsum[b];
        }
        if (blockIdx.x == 0) g_off[NN] = run;
    }
    __syncthreads();
    int i = blockIdx.x * 1024 + tid;
    if (i < NN) {
        int o = g_off[i] + s_pre;
        g_off[i] = o;
        g_cur[i] = o;
    }
}

// ---------------- CSR fill ----------------
__global__ void k_fill(const int* __restrict__ ei) {
    int e = blockIdx.x * blockDim.x + threadIdx.x;
    if (e < EE) {
        int d = ei[EE + e];
        int slot = atomicAdd(&g_cur[d], 1);
        g_srcs[slot] = ei[e];
    }
}

// ---------------- conv GEMM (k-pair f32x2): bufA = (X*rout) @ W  (Nx128 @ 128x128)
__global__ void __launch_bounds__(256, 2)
k_gemm128(const float* __restrict__ Xext, const float* __restrict__ W, int useB) {
    extern __shared__ float sm[];
    float* Ws2 = sm;              // 128*128 floats (64 kp x 128 cols x float2)
    float* Xs  = sm + DD * DD;    // 64*128
    const float* X = useB ? (const float*)g_bufB : Xext;

    int tid = threadIdx.x;
    int m0  = blockIdx.x * 64;

    {
        float2* Wd = (float2*)Ws2;
        #pragma unroll
        for (int q = 0; q < 32; q++) {
            int idx = tid + 256 * q;          // 0..8191
            int kp = idx >> 7, c = idx & 127;
            Wd[idx] = make_float2(W[(2 * kp) * DD + c], W[(2 * kp + 1) * DD + c]);
        }
    }
    {
        int r  = tid >> 2;
        int c4 = tid & 3;
        int gi = m0 + r;
        float4* Xd = (float4*)(Xs + r * DD);
        if (gi < NN) {
            float sc = g_rout[gi];
            const float4* Xr = (const float4*)(X + (size_t)gi * DD);
            #pragma unroll
            for (int q = 0; q < 8; q++) {
                float4 v = Xr[c4 + 4 * q];
                v.x *= sc; v.y *= sc; v.z *= sc; v.w *= sc;
                Xd[c4 + 4 * q] = v;
            }
        } else {
            #pragma unroll
            for (int q = 0; q < 8; q++) Xd[c4 + 4 * q] = make_float4(0.f, 0.f, 0.f, 0.f);
        }
    }
    __syncthreads();

    int ty = tid >> 5, tx = tid & 31;
    const ull* Wp = (const ull*)Ws2;            // [kp*128 + col]
    ull acc[8][4];
    #pragma unroll
    for (int r = 0; r < 8; r++)
        #pragma unroll
        for (int c = 0; c < 4; c++) acc[r][c] = 0ull;

    #pragma unroll 8
    for (int kp = 0; kp < DD / 2; kp++) {
        ulonglong2 bb0 = *(const ulonglong2*)(Wp + kp * DD + 4 * tx);
        ulonglong2 bb1 = *(const ulonglong2*)(Wp + kp * DD + 4 * tx + 2);
        ull a2[8];
        #pragma unroll
        for (int r = 0; r < 8; r++)
            a2[r] = *(const ull*)(Xs + (ty * 8 + r) * DD + 2 * kp);   // broadcast
        #pragma unroll
        for (int r = 0; r < 8; r++) {
            FMA2(acc[r][0], a2[r], bb0.x);
            FMA2(acc[r][1], a2[r], bb0.y);
            FMA2(acc[r][2], a2[r], bb1.x);
            FMA2(acc[r][3], a2[r], bb1.y);
        }
    }

    #pragma unroll
    for (int r = 0; r < 8; r++) {
        int gi = m0 + ty * 8 + r;
        if (gi < NN) {
            float4 o;
            float lo, hi;
            UNPACK2(lo, hi, acc[r][0]); o.x = lo + hi;
            UNPACK2(lo, hi, acc[r][1]); o.y = lo + hi;
            UNPACK2(lo, hi, acc[r][2]); o.z = lo + hi;
            UNPACK2(lo, hi, acc[r][3]); o.w = lo + hi;
            *(float4*)(g_bufA + (size_t)gi * DD + 4 * tx) = o;
        }
    }
}

// ---------------- aggregation: bufB[i] = rin[i]*sum_{in(i)} bufA[src] + b ----
__global__ void k_agg(const float* __restrict__ bias) {
    int t = blockIdx.x * blockDim.x + threadIdx.x;
    int w = t >> 5, lane = t & 31;
    if (w >= NN) return;
    int lo = g_off[w], hi = g_off[w + 1];
    float4 acc = make_float4(0.f, 0.f, 0.f, 0.f);
    for (int j = lo; j < hi; j++) {
        int s = g_srcs[j];
        float4 v = *(const float4*)(g_bufA + (size_t)s * DD + lane * 4);
        acc.x += v.x; acc.y += v.y; acc.z += v.z; acc.w += v.w;
    }
    float r = g_rin[w];
    float4 bb = *(const float4*)(bias + lane * 4);
    float4 o;
    o.x = acc.x * r + bb.x; o.y = acc.y * r + bb.y;
    o.z = acc.z * r + bb.z; o.w = acc.w * r + bb.w;
    *(float4*)(g_bufB + (size_t)w * DD + lane * 4) = o;
}

// ---------------- PERSISTENT fused gather + dense + relu + out + softmax -----
// 148 blocks x 256 threads. W staged ONCE per block; grid-stride over M-tiles.
// Per thread: 8 rows (warp wid -> rows 8wid..8wid+7) x 8 cols (col = 32c+lane).
// k-pair f32x2: acc lane0 = even-k partial, lane1 = odd-k partial.
__global__ void __launch_bounds__(256, 1)
k_final(const int* __restrict__ set_idx,
        const int* __restrict__ oe,
        const float* __restrict__ dW,
        const float* __restrict__ db,
        const float* __restrict__ oW,
        const float* __restrict__ ob,
        float* __restrict__ out) {
    extern __shared__ float sm[];
    float* Ws2  = sm;                  // 128*256 floats (64 kp x 256 cols x float2)
    float* Xs   = Ws2 + DD * UD;       // 64*128
    float* s_db = Xs + 64 * DD;        // 256
    float* s_oW = s_db + UD;           // 512
    __shared__ float s_ob[2];

    int tid  = threadIdx.x;
    int wid  = tid >> 5;
    int lane = tid & 31;

    // stage dense_W once, k-pair interleaved: Wd[kp*256+c] = (dW[2kp][c], dW[2kp+1][c])
    {
        float2* Wd = (float2*)Ws2;
        #pragma unroll
        for (int q = 0; q < 64; q++) {
            int idx = tid + 256 * q;          // 0..16383
            int kp = idx >> 8, c = idx & 255;
            Wd[idx] = make_float2(dW[(2 * kp) * UD + c], dW[(2 * kp + 1) * UD + c]);
        }
    }
    if (tid < UD) {
        s_db[tid]         = db[tid];
        s_oW[tid * 2]     = oW[tid * 2];
        s_oW[tid * 2 + 1] = oW[tid * 2 + 1];
    }
    if (tid < 2) s_ob[tid] = ob[tid];

    const ull* Wp = (const ull*)Ws2;            // [kp*256 + col]
    const int n_tiles = (NSEL + 63) / 64;

    for (int tile = blockIdx.x; tile < n_tiles; tile += NSM) {
        int m0 = tile * 64;
        __syncthreads();   // previous tile fully consumed Xs

        // gather 64 rows of h2 into Xs
        {
            int r  = tid >> 2;
            int c4 = tid & 3;
            int gi = m0 + r;
            float4* Xd = (float4*)(Xs + r * DD);
            if (gi < NSEL) {
                int s    = set_idx[gi];
                int node = oe[s];
                const float4* Hs = (const float4*)(g_bufB + (size_t)node * DD);
                #pragma unroll
                for (int q = 0; q < 8; q++) Xd[c4 + 4 * q] = Hs[c4 + 4 * q];
            } else {
                #pragma unroll
                for (int q = 0; q < 8; q++) Xd[c4 + 4 * q] = make_float4(0.f, 0.f, 0.f, 0.f);
            }
        }
        __syncthreads();

        ull acc[8][8];
        #pragma unroll
        for (int r = 0; r < 8; r++)
            #pragma unroll
            for (int c = 0; c < 8; c++) acc[r][c] = 0ull;

        #pragma unroll 4
        for (int kp = 0; kp < DD / 2; kp++) {
            ull b2[8];
            #pragma unroll
            for (int c = 0; c < 8; c++)
                b2[c] = Wp[kp * UD + 32 * c + lane];        // conflict-free LDS.64
            ull a2[8];
            #pragma unroll
            for (int r = 0; r < 8; r++)
                a2[r] = *(const ull*)(Xs + (wid * 8 + r) * DD + 2 * kp);  // broadcast
            #pragma unroll
            for (int r = 0; r < 8; r++)
                #pragma unroll
                for (int c = 0; c < 8; c++)
                    FMA2(acc[r][c], a2[r], b2[c]);
        }

        // epilogue: each warp owns rows 8wid..8wid+7 across ALL 256 cols
        #pragma unroll
        for (int r = 0; r < 8; r++) {
            float p0 = 0.f, p1 = 0.f;
            #pragma unroll
            for (int c = 0; c < 8; c++) {
                float lo, hi;
                UNPACK2(lo, hi, acc[r][c]);
                int col = 32 * c + lane;
                float v = fmaxf(lo + hi + s_db[col], 0.f);
                p0 = fmaf(v, s_oW[col * 2],     p0);
                p1 = fmaf(v, s_oW[col * 2 + 1], p1);
            }
            #pragma unroll
            for (int o = 16; o; o >>= 1) {
                p0 += __shfl_down_sync(0xffffffffu, p0, o);
                p1 += __shfl_down_sync(0xffffffffu, p1, o);
            }
            if (lane == 0) {
                int gi = m0 + wid * 8 + r;
                if (gi < NSEL) {
                    float z0 = p0 + s_ob[0], z1 = p1 + s_ob[1];
                    float m  = fmaxf(z0, z1);
                    float e0 = __expf(z0 - m), e1 = __expf(z1 - m);
                    float inv = 1.f / (e0 + e1);
                    out[(size_t)gi * 2]     = e0 * inv;
                    out[(size_t)gi * 2 + 1] = e1 * inv;
                }
            }
        }
    }
}

// ---------------- host launch ----------------
extern "C" void kernel_launch(void* const* d_in, const int* in_sizes, int n_in,
                              void* d_out, int out_size) {
    const float* node_state = (const float*)d_in[0];
    const int*   edge_index = (const int*)d_in[1];
    const int*   out_edges  = (const int*)d_in[2];
    const int*   set_idx    = (const int*)d_in[3];
    const float* W1         = (const float*)d_in[4];
    const float* b1         = (const float*)d_in[5];
    const float* W2         = (const float*)d_in[6];
    const float* b2         = (const float*)d_in[7];
    const float* dW         = (const float*)d_in[8];
    const float* db         = (const float*)d_in[9];
    const float* oW         = (const float*)d_in[10];
    const float* ob         = (const float*)d_in[11];
    float* out = (float*)d_out;

    const int GEMM_SMEM  = (DD * DD + 64 * DD) * 4;                  // 96 KB
    const int FINAL_SMEM = (DD * UD + 64 * DD + UD + 2 * UD) * 4;    // ~163 KB

    cudaFuncSetAttribute(k_gemm128, cudaFuncAttributeMaxDynamicSharedMemorySize, GEMM_SMEM);
    cudaFuncSetAttribute(k_final,   cudaFuncAttributeMaxDynamicSharedMemorySize, FINAL_SMEM);

    // launch order tuned so ncu's fixed "-s 5 -c 1" captures k_gemm128 (#6)
    k_zero   <<<(NN + 255) / 256, 256>>>();                          // 1
    k_count  <<<(EE + 255) / 256, 256>>>(edge_index);                // 2
    k_scan_a <<<NB, 1024>>>();                                       // 3 (+rsqrt)
    k_scan_c <<<NB, 1024>>>();                                       // 4 (+block-sum scan)
    k_fill   <<<(EE + 255) / 256, 256>>>(edge_index);                // 5

    k_gemm128<<<(NN + 63) / 64, 256, GEMM_SMEM>>>(node_state, W1, 0); // 6 <- profiled
    k_agg    <<<(NN * 32 + 255) / 256, 256>>>(b1);
    k_gemm128<<<(NN + 63) / 64, 256, GEMM_SMEM>>>(nullptr, W2, 1);
    k_agg    <<<(NN * 32 + 255) / 256, 256>>>(b2);

    k_final<<<NSM, 256, FINAL_SMEM>>>(set_idx, out_edges, dW, db, oW, ob, out);
}

// round 8
// speedup vs baseline: 3.3435x; 2.5126x over previous
#include <cuda_runtime.h>

#define NN    50000
#define DD    128
#define EE    600000
#define NPRED 200000
#define NSEL  300000
#define UD    256
#define NB    49          // scan blocks: 49*1024 >= NN
#define NSM   148

typedef unsigned long long ull;

// packed f32x2 helpers (sm_103a FFMA2 — only reachable via PTX)
#define FMA2(d, a, b) asm("fma.rn.f32x2 %0, %1, %2, %0;" : "+l"(d) : "l"(a), "l"(b))
#define UNPACK2(lo, hi, s) asm("mov.b64 {%0, %1}, %2;" : "=f"(lo), "=f"(hi) : "l"(s))

// ---------------- scratch (device globals: allocation-free) ----------------
__device__ int   g_deg_in[NN];
__device__ int   g_deg_out[NN];
__device__ float g_rin[NN];
__device__ float g_rout[NN];
__device__ int   g_off[NN + 1];
__device__ int   g_cur[NN];
__device__ int   g_srcs[EE];
__device__ int   g_bsum[NB];
__device__ float g_bufA[(size_t)NN * DD];
__device__ float g_bufB[(size_t)NN * DD];
__device__ float g_prob[(size_t)NN * 2];

// ---------------- degree counting ----------------
__global__ void k_zero() {
    int i = blockIdx.x * blockDim.x + threadIdx.x;
    if (i < NN) { g_deg_in[i] = 0; g_deg_out[i] = 0; }
}

__global__ void k_count(const int* __restrict__ ei) {
    int e = blockIdx.x * blockDim.x + threadIdx.x;
    if (e < EE) {
        atomicAdd(&g_deg_out[ei[e]], 1);
        atomicAdd(&g_deg_in[ei[EE + e]], 1);
    }
}

// ---------------- scan pass A (+ fused rsqrt of both degree arrays) ----------
__global__ void k_scan_a() {
    __shared__ int wsum[32];
    int tid  = threadIdx.x;
    int i    = blockIdx.x * 1024 + tid;
    int lane = tid & 31, wid = tid >> 5;
    int v = (i < NN) ? g_deg_in[i] : 0;

    if (i < NN) {
        int dout = g_deg_out[i]; if (dout < 1) dout = 1;
        int din  = v;            if (din  < 1) din  = 1;
        g_rout[i] = rsqrtf((float)dout);
        g_rin[i]  = rsqrtf((float)din);
    }

    int x = v;
    #pragma unroll
    for (int s = 1; s < 32; s <<= 1) {
        int t = __shfl_up_sync(0xffffffffu, x, s);
        if (lane >= s) x += t;
    }
    if (lane == 31) wsum[wid] = x;
    __syncthreads();
    if (wid == 0) {
        int y = wsum[lane];
        #pragma unroll
        for (int s = 1; s < 32; s <<= 1) {
            int t = __shfl_up_sync(0xffffffffu, y, s);
            if (lane >= s) y += t;
        }
        wsum[lane] = y;
    }
    __syncthreads();

    int excl = x - v + (wid ? wsum[wid - 1] : 0);
    if (i < NN) g_off[i] = excl;
    if (tid == 1023) g_bsum[blockIdx.x] = excl + v;
}

// ---------------- scan pass C (fused block-sum scan, redundant per block) ----
__global__ void k_scan_c() {
    __shared__ int s_pre;
    int tid = threadIdx.x;
    if (tid == 0) {
        int run = 0;
        #pragma unroll
        for (int b = 0; b < NB; b++) {
            if (b == blockIdx.x) s_pre = run;
            run += g_bsum[b];
        }
        if (blockIdx.x == 0) g_off[NN] = run;
    }
    __syncthreads();
    int i = blockIdx.x * 1024 + tid;
    if (i < NN) {
        int o = g_off[i] + s_pre;
        g_off[i] = o;
        g_cur[i] = o;
    }
}

// ---------------- CSR fill ----------------
__global__ void k_fill(const int* __restrict__ ei) {
    int e = blockIdx.x * blockDim.x + threadIdx.x;
    if (e < EE) {
        int d = ei[EE + e];
        int slot = atomicAdd(&g_cur[d], 1);
        g_srcs[slot] = ei[e];
    }
}

// ---------------- conv GEMM (k-pair f32x2): bufA = (X*rout) @ W  (Nx128 @ 128x128)
__global__ void __launch_bounds__(256, 2)
k_gemm128(const float* __restrict__ Xext, const float* __restrict__ W, int useB) {
    extern __shared__ float sm[];
    float* Ws2 = sm;              // 128*128 floats (64 kp x 128 cols x float2)
    float* Xs  = sm + DD * DD;    // 64*128
    const float* X = useB ? (const float*)g_bufB : Xext;

    int tid = threadIdx.x;
    int m0  = blockIdx.x * 64;

    {
        float2* Wd = (float2*)Ws2;
        #pragma unroll
        for (int q = 0; q < 32; q++) {
            int idx = tid + 256 * q;          // 0..8191
            int kp = idx >> 7, c = idx & 127;
            Wd[idx] = make_float2(W[(2 * kp) * DD + c], W[(2 * kp + 1) * DD + c]);
        }
    }
    {
        int r  = tid >> 2;
        int c4 = tid & 3;
        int gi = m0 + r;
        float4* Xd = (float4*)(Xs + r * DD);
        if (gi < NN) {
            float sc = g_rout[gi];
            const float4* Xr = (const float4*)(X + (size_t)gi * DD);
            #pragma unroll
            for (int q = 0; q < 8; q++) {
                float4 v = Xr[c4 + 4 * q];
                v.x *= sc; v.y *= sc; v.z *= sc; v.w *= sc;
                Xd[c4 + 4 * q] = v;
            }
        } else {
            #pragma unroll
            for (int q = 0; q < 8; q++) Xd[c4 + 4 * q] = make_float4(0.f, 0.f, 0.f, 0.f);
        }
    }
    __syncthreads();

    int ty = tid >> 5, tx = tid & 31;
    const ull* Wp = (const ull*)Ws2;            // [kp*128 + col]
    ull acc[8][4];
    #pragma unroll
    for (int r = 0; r < 8; r++)
        #pragma unroll
        for (int c = 0; c < 4; c++) acc[r][c] = 0ull;

    #pragma unroll 8
    for (int kp = 0; kp < DD / 2; kp++) {
        ulonglong2 bb0 = *(const ulonglong2*)(Wp + kp * DD + 4 * tx);
        ulonglong2 bb1 = *(const ulonglong2*)(Wp + kp * DD + 4 * tx + 2);
        ull a2[8];
        #pragma unroll
        for (int r = 0; r < 8; r++)
            a2[r] = *(const ull*)(Xs + (ty * 8 + r) * DD + 2 * kp);   // broadcast
        #pragma unroll
        for (int r = 0; r < 8; r++) {
            FMA2(acc[r][0], a2[r], bb0.x);
            FMA2(acc[r][1], a2[r], bb0.y);
            FMA2(acc[r][2], a2[r], bb1.x);
            FMA2(acc[r][3], a2[r], bb1.y);
        }
    }

    #pragma unroll
    for (int r = 0; r < 8; r++) {
        int gi = m0 + ty * 8 + r;
        if (gi < NN) {
            float4 o;
            float lo, hi;
            UNPACK2(lo, hi, acc[r][0]); o.x = lo + hi;
            UNPACK2(lo, hi, acc[r][1]); o.y = lo + hi;
            UNPACK2(lo, hi, acc[r][2]); o.z = lo + hi;
            UNPACK2(lo, hi, acc[r][3]); o.w = lo + hi;
            *(float4*)(g_bufA + (size_t)gi * DD + 4 * tx) = o;
        }
    }
}

// ---------------- aggregation: bufB[i] = rin[i]*sum_{in(i)} bufA[src] + b ----
__global__ void k_agg(const float* __restrict__ bias) {
    int t = blockIdx.x * blockDim.x + threadIdx.x;
    int w = t >> 5, lane = t & 31;
    if (w >= NN) return;
    int lo = g_off[w], hi = g_off[w + 1];
    float4 acc = make_float4(0.f, 0.f, 0.f, 0.f);
    for (int j = lo; j < hi; j++) {
        int s = g_srcs[j];
        float4 v = *(const float4*)(g_bufA + (size_t)s * DD + lane * 4);
        acc.x += v.x; acc.y += v.y; acc.z += v.z; acc.w += v.w;
    }
    float r = g_rin[w];
    float4 bb = *(const float4*)(bias + lane * 4);
    float4 o;
    o.x = acc.x * r + bb.x; o.y = acc.y * r + bb.y;
    o.z = acc.z * r + bb.z; o.w = acc.w * r + bb.w;
    *(float4*)(g_bufB + (size_t)w * DD + lane * 4) = o;
}

// ---------------- PERSISTENT per-NODE head: dense(128->256)+relu+out+softmax --
// KEY: hidden/logits depend only on the node, so compute P[node] for 50K nodes
// (6x fewer rows than the 300K selections), then k_out gathers 2 floats/row.
// 148 blocks x 256 threads. W staged ONCE; grid-stride over 782 64-row tiles.
// Per thread: 8 rows (warp wid -> rows 8wid..8wid+7) x 8 cols (col = 32c+lane).
__global__ void __launch_bounds__(256, 1)
k_dense(const float* __restrict__ dW,
        const float* __restrict__ db,
        const float* __restrict__ oW,
        const float* __restrict__ ob) {
    extern __shared__ float sm[];
    float* Ws2  = sm;                  // 128*256 floats (64 kp x 256 cols x float2)
    float* Xs   = Ws2 + DD * UD;       // 64*128
    float* s_db = Xs + 64 * DD;        // 256
    float* s_oW = s_db + UD;           // 512
    __shared__ float s_ob[2];

    int tid  = threadIdx.x;
    int wid  = tid >> 5;
    int lane = tid & 31;

    // stage dense_W once, k-pair interleaved: Wd[kp*256+c] = (dW[2kp][c], dW[2kp+1][c])
    {
        float2* Wd = (float2*)Ws2;
        #pragma unroll
        for (int q = 0; q < 64; q++) {
            int idx = tid + 256 * q;          // 0..16383
            int kp = idx >> 8, c = idx & 255;
            Wd[idx] = make_float2(dW[(2 * kp) * UD + c], dW[(2 * kp + 1) * UD + c]);
        }
    }
    if (tid < UD) {
        s_db[tid]         = db[tid];
        s_oW[tid * 2]     = oW[tid * 2];
        s_oW[tid * 2 + 1] = oW[tid * 2 + 1];
    }
    if (tid < 2) s_ob[tid] = ob[tid];

    const ull* Wp = (const ull*)Ws2;            // [kp*256 + col]
    const int n_tiles = (NN + 63) / 64;         // 782

    for (int tile = blockIdx.x; tile < n_tiles; tile += NSM) {
        int m0 = tile * 64;
        __syncthreads();   // previous tile fully consumed Xs

        // load 64 node rows (sequential — no gather needed)
        {
            int r  = tid >> 2;
            int c4 = tid & 3;
            int gi = m0 + r;
            float4* Xd = (float4*)(Xs + r * DD);
            if (gi < NN) {
                const float4* Hs = (const float4*)(g_bufB + (size_t)gi * DD);
                #pragma unroll
                for (int q = 0; q < 8; q++) Xd[c4 + 4 * q] = Hs[c4 + 4 * q];
            } else {
                #pragma unroll
                for (int q = 0; q < 8; q++) Xd[c4 + 4 * q] = make_float4(0.f, 0.f, 0.f, 0.f);
            }
        }
        __syncthreads();

        ull acc[8][8];
        #pragma unroll
        for (int r = 0; r < 8; r++)
            #pragma unroll
            for (int c = 0; c < 8; c++) acc[r][c] = 0ull;

        #pragma unroll 4
        for (int kp = 0; kp < DD / 2; kp++) {
            ull b2[8];
            #pragma unroll
            for (int c = 0; c < 8; c++)
                b2[c] = Wp[kp * UD + 32 * c + lane];        // conflict-free LDS.64
            ull a2[8];
            #pragma unroll
            for (int r = 0; r < 8; r++)
                a2[r] = *(const ull*)(Xs + (wid * 8 + r) * DD + 2 * kp);  // broadcast
            #pragma unroll
            for (int r = 0; r < 8; r++)
                #pragma unroll
                for (int c = 0; c < 8; c++)
                    FMA2(acc[r][c], a2[r], b2[c]);
        }

        // epilogue: relu + 256->2, warp-reduce, softmax -> g_prob[node]
        #pragma unroll
        for (int r = 0; r < 8; r++) {
            float p0 = 0.f, p1 = 0.f;
            #pragma unroll
            for (int c = 0; c < 8; c++) {
                float lo, hi;
                UNPACK2(lo, hi, acc[r][c]);
                int col = 32 * c + lane;
                float v = fmaxf(lo + hi + s_db[col], 0.f);
                p0 = fmaf(v, s_oW[col * 2],     p0);
                p1 = fmaf(v, s_oW[col * 2 + 1], p1);
            }
            #pragma unroll
            for (int o = 16; o; o >>= 1) {
                p0 += __shfl_down_sync(0xffffffffu, p0, o);
                p1 += __shfl_down_sync(0xffffffffu, p1, o);
            }
            if (lane == 0) {
                int gi = m0 + wid * 8 + r;
                if (gi < NN) {
                    float z0 = p0 + s_ob[0], z1 = p1 + s_ob[1];
                    float m  = fmaxf(z0, z1);
                    float e0 = __expf(z0 - m), e1 = __expf(z1 - m);
                    float inv = 1.f / (e0 + e1);
                    *(float2*)(g_prob + (size_t)gi * 2) = make_float2(e0 * inv, e1 * inv);
                }
            }
        }
    }
}

// ---------------- output gather: out[i] = P[oe[set_idx[i]]] ----------------
__global__ void k_out(const int* __restrict__ set_idx,
                      const int* __restrict__ oe,
                      float* __restrict__ out) {
    int i = blockIdx.x * blockDim.x + threadIdx.x;
    if (i < NSEL) {
        int node = oe[set_idx[i]];
        *(float2*)(out + (size_t)i * 2) = *(const float2*)(g_prob + (size_t)node * 2);
    }
}

// ---------------- host launch ----------------
extern "C" void kernel_launch(void* const* d_in, const int* in_sizes, int n_in,
                              void* d_out, int out_size) {
    const float* node_state = (const float*)d_in[0];
    const int*   edge_index = (const int*)d_in[1];
    const int*   out_edges  = (const int*)d_in[2];
    const int*   set_idx    = (const int*)d_in[3];
    const float* W1         = (const float*)d_in[4];
    const float* b1         = (const float*)d_in[5];
    const float* W2         = (const float*)d_in[6];
    const float* b2         = (const float*)d_in[7];
    const float* dW         = (const float*)d_in[8];
    const float* db         = (const float*)d_in[9];
    const float* oW         = (const float*)d_in[10];
    const float* ob         = (const float*)d_in[11];
    float* out = (float*)d_out;

    const int GEMM_SMEM  = (DD * DD + 64 * DD) * 4;                  // 96 KB
    const int DENSE_SMEM = (DD * UD + 64 * DD + UD + 2 * UD) * 4;    // ~163 KB

    cudaFuncSetAttribute(k_gemm128, cudaFuncAttributeMaxDynamicSharedMemorySize, GEMM_SMEM);
    cudaFuncSetAttribute(k_dense,   cudaFuncAttributeMaxDynamicSharedMemorySize, DENSE_SMEM);

    // launch order keeps k_gemm128 as launch #6 for ncu's fixed "-s 5 -c 1"
    k_zero   <<<(NN + 255) / 256, 256>>>();                          // 1
    k_count  <<<(EE + 255) / 256, 256>>>(edge_index);                // 2
    k_scan_a <<<NB, 1024>>>();                                       // 3
    k_scan_c <<<NB, 1024>>>();                                       // 4
    k_fill   <<<(EE + 255) / 256, 256>>>(edge_index);                // 5

    k_gemm128<<<(NN + 63) / 64, 256, GEMM_SMEM>>>(node_state, W1, 0); // 6 <- profiled
    k_agg    <<<(NN * 32 + 255) / 256, 256>>>(b1);
    k_gemm128<<<(NN + 63) / 64, 256, GEMM_SMEM>>>(nullptr, W2, 1);
    k_agg    <<<(NN * 32 + 255) / 256, 256>>>(b2);

    k_dense<<<NSM, 256, DENSE_SMEM>>>(dW, db, oW, ob);
    k_out  <<<(NSEL + 255) / 256, 256>>>(set_idx, out_edges, out);
}